// round 9
// baseline (speedup 1.0000x reference)
#include <cuda_runtime.h>
#include <math.h>
#include <stdint.h>

#define T_TOKENS 8192
#define DM 1024
#define DF 4096
#define N_EXP 8

// ---------------- scratch (__device__ globals) ------------------------------
__device__ int      g_counts[N_EXP];
__device__ int      g_offsets[N_EXP];
__device__ int      g_tok[N_EXP * T_TOKENS];
__device__ float    g_w[N_EXP * T_TOKENS];
__device__ unsigned g_H[(size_t)16384 * DF];          // tf32 bit image
__device__ unsigned g_W1t[(size_t)N_EXP * DM * DF];   // tf32 bit image of W1
__device__ unsigned g_W2t[(size_t)N_EXP * DF * DM];   // tf32 bit image of W2
__device__ unsigned g_xt[(size_t)T_TOKENS * DM];      // tf32 bit image of x

// ---------------- helpers ----------------------------------------------------
__device__ __forceinline__ unsigned f2tf32(float f) {
    unsigned u;
    asm("cvt.rna.tf32.f32 %0, %1;" : "=r"(u) : "f"(f));
    return u;
}

__device__ __forceinline__ void mma_tf32(float c[4], const unsigned a[4], const unsigned b[2]) {
    asm volatile(
        "mma.sync.aligned.m16n8k8.row.col.f32.tf32.tf32.f32 "
        "{%0,%1,%2,%3}, {%4,%5,%6,%7}, {%8,%9}, {%0,%1,%2,%3};\n"
        : "+f"(c[0]), "+f"(c[1]), "+f"(c[2]), "+f"(c[3])
        : "r"(a[0]), "r"(a[1]), "r"(a[2]), "r"(a[3]), "r"(b[0]), "r"(b[1]));
}

__device__ __forceinline__ float gelu_exact(float v) {
    return 0.5f * v * (1.0f + erff(v * 0.70710678118654752f));
}

__device__ __forceinline__ unsigned smem_u32(const void* p) {
    unsigned a;
    asm("{ .reg .u64 t; cvta.to.shared.u64 t, %1; cvt.u32.u64 %0, t; }"
        : "=r"(a) : "l"(p));
    return a;
}

#define CP_ASYNC16(dst, src, sz) \
    asm volatile("cp.async.cg.shared.global [%0], [%1], 16, %2;" \
                 :: "r"(dst), "l"(src), "r"(sz) : "memory")
#define CP_COMMIT() asm volatile("cp.async.commit_group;" ::: "memory")
#define CP_WAIT(n)  asm volatile("cp.async.wait_group %0;" :: "n"(n) : "memory")

// ---------------- conversion: f32 -> tf32 bit image ---------------------------
__global__ void conv_kernel(const float4* __restrict__ s, uint4* __restrict__ d, int n4) {
    int i = blockIdx.x * blockDim.x + threadIdx.x;
    if (i < n4) {
        float4 v = s[i];
        uint4 u;
        u.x = f2tf32(v.x); u.y = f2tf32(v.y);
        u.z = f2tf32(v.z); u.w = f2tf32(v.w);
        d[i] = u;
    }
}

// ---------------- zero out + counters ----------------------------------------
__global__ void zero_kernel(float* __restrict__ out, int n4) {
    int i = blockIdx.x * blockDim.x + threadIdx.x;
    if (i < n4) reinterpret_cast<float4*>(out)[i] = make_float4(0.f, 0.f, 0.f, 0.f);
    if (i < N_EXP) g_counts[i] = 0;
}

// ---------------- gating: one warp per token ---------------------------------
__global__ void gating_kernel(const float* __restrict__ x,
                              const float* __restrict__ Wg,
                              const float* __restrict__ bg,
                              float* __restrict__ logits_out,
                              int write_logits) {
    int warp = threadIdx.x >> 5;
    int lane = threadIdx.x & 31;
    int t = blockIdx.x * (blockDim.x >> 5) + warp;
    if (t >= T_TOKENS) return;

    float acc[8];
#pragma unroll
    for (int e = 0; e < 8; e++) acc[e] = 0.f;

    const float4* x4 = reinterpret_cast<const float4*>(x + (size_t)t * DM);
#pragma unroll
    for (int j = 0; j < 8; j++) {
        int idx4 = j * 32 + lane;
        float4 v = x4[idx4];
        float vv[4] = {v.x, v.y, v.z, v.w};
        int i = idx4 * 4;
#pragma unroll
        for (int c = 0; c < 4; c++) {
            const float4* w4 = reinterpret_cast<const float4*>(Wg + (size_t)(i + c) * 8);
            float4 wa = w4[0], wb = w4[1];
            acc[0] += vv[c] * wa.x; acc[1] += vv[c] * wa.y;
            acc[2] += vv[c] * wa.z; acc[3] += vv[c] * wa.w;
            acc[4] += vv[c] * wb.x; acc[5] += vv[c] * wb.y;
            acc[6] += vv[c] * wb.z; acc[7] += vv[c] * wb.w;
        }
    }
#pragma unroll
    for (int e = 0; e < 8; e++)
#pragma unroll
        for (int o = 16; o > 0; o >>= 1)
            acc[e] += __shfl_xor_sync(0xffffffffu, acc[e], o);

    if (lane == 0) {
        float lg[8];
#pragma unroll
        for (int e = 0; e < 8; e++) lg[e] = acc[e] + bg[e];
        if (write_logits) {
#pragma unroll
            for (int e = 0; e < 8; e++) logits_out[(size_t)t * 8 + e] = lg[e];
        }
        float mx = lg[0];
#pragma unroll
        for (int e = 1; e < 8; e++) mx = fmaxf(mx, lg[e]);
        float p[8], s = 0.f;
#pragma unroll
        for (int e = 0; e < 8; e++) { p[e] = expf(lg[e] - mx); s += p[e]; }
        int i1 = 0;
#pragma unroll
        for (int e = 1; e < 8; e++) if (p[e] > p[i1]) i1 = e;
        int i2 = -1;
#pragma unroll
        for (int e = 0; e < 8; e++) {
            if (e == i1) continue;
            if (i2 < 0 || p[e] > p[i2]) i2 = e;
        }
        float w1 = p[i1] / s, w2 = p[i2] / s;
        int pos1 = atomicAdd(&g_counts[i1], 1);
        g_tok[i1 * T_TOKENS + pos1] = t;
        g_w[i1 * T_TOKENS + pos1] = w1;
        int pos2 = atomicAdd(&g_counts[i2], 1);
        g_tok[i2 * T_TOKENS + pos2] = t;
        g_w[i2 * T_TOKENS + pos2] = w2;
    }
}

__global__ void scan_kernel() {
    if (threadIdx.x == 0 && blockIdx.x == 0) {
        int s = 0;
        for (int e = 0; e < N_EXP; e++) { g_offsets[e] = s; s += g_counts[e]; }
    }
}

// ---------------- tiled tf32 GEMM: 128x128 CTA, 4 warps of 64x64 --------------
// cp.async 3-stage pipeline; operands pre-converted tf32 (no cvt in hot loop).
#define BM 128
#define BN 128
#define BK 16
#define SA 20    // A smem row stride (words)
#define SB 136   // B smem row stride (words)
#define NTHR 128
#define NSTG 3

// IS_G1=1: A = g_xt gathered by token, out = g_H (gelu+b1, tf32 bits)
// IS_G1=0: A = g_H rows,               out = atomic combine into out (b2, weights)
template<int IS_G1>
__global__ __launch_bounds__(NTHR, 3) void moe_gemm_fb(
    const unsigned* __restrict__ Asrc0,
    const unsigned* __restrict__ Wt,
    const float* __restrict__ bias,
    float* __restrict__ out)
{
    constexpr int KTOT = IS_G1 ? DM : DF;
    constexpr int NTOT = IS_G1 ? DF : DM;

    int e = blockIdx.z;
    int cnt = g_counts[e];
    int m0 = blockIdx.y * BM;
    if (m0 >= cnt) return;
    int n0 = blockIdx.x * BN;
    int off = g_offsets[e];
    const unsigned* W = Wt + (size_t)e * KTOT * NTOT;
    const unsigned* A = IS_G1 ? Asrc0 : g_H;

    __shared__ unsigned As[NSTG][BM * SA];
    __shared__ unsigned Bs[NSTG][BK * SB];

    int tid = threadIdx.x;
    int warp = tid >> 5, lane = tid & 31;
    int wm = (warp >> 1) * 64, wn = (warp & 1) * 64;
    int lr = lane >> 2, lc = lane & 3;

    unsigned aBase = smem_u32(&As[0][0]);
    unsigned bBase = smem_u32(&Bs[0][0]);

    // A-load rows: r = tid>>2 + h*32 for h = 0..3
    int rowv[4];
#pragma unroll
    for (int h = 0; h < 4; h++) {
        int r = (tid >> 2) + h * 32;
        int grow = m0 + r;
        if (grow >= cnt) rowv[h] = -1;
        else rowv[h] = IS_G1 ? g_tok[e * T_TOKENS + grow] : (off + grow);
    }

    float acc[4][8][4];
#pragma unroll
    for (int im = 0; im < 4; im++)
#pragma unroll
        for (int in_ = 0; in_ < 8; in_++)
#pragma unroll
            for (int q = 0; q < 4; q++) acc[im][in_][q] = 0.f;

    auto issue = [&](int kt, int stg) {
        int k0 = kt * BK;
        unsigned abuf = aBase + stg * (BM * SA * 4);
        unsigned bbuf = bBase + stg * (BK * SB * 4);
#pragma unroll
        for (int h = 0; h < 4; h++) {
            int r = (tid >> 2) + h * 32;
            unsigned dst = abuf + r * (SA * 4) + (tid & 3) * 16;
            int rv = rowv[h];
            const unsigned* src = A + (size_t)(rv < 0 ? 0 : rv) * KTOT + k0 + (tid & 3) * 4;
            int sz = (rv < 0) ? 0 : 16;
            CP_ASYNC16(dst, src, sz);
        }
#pragma unroll
        for (int h = 0; h < 4; h++) {
            int idx = tid + h * NTHR;
            int k = idx >> 5, c = (idx & 31) * 4;
            unsigned dst = bbuf + k * (SB * 4) + c * 4;
            const unsigned* src = W + (size_t)(k0 + k) * NTOT + n0 + c;
            CP_ASYNC16(dst, src, 16);
        }
    };

    const int nk = KTOT / BK;
    issue(0, 0); CP_COMMIT();
    issue(1, 1); CP_COMMIT();

    for (int kt = 0; kt < nk; kt++) {
        int stg = kt % NSTG;
        CP_WAIT(1);
        __syncthreads();
        int nxt = kt + 2;
        if (nxt < nk) { issue(nxt, nxt % NSTG); CP_COMMIT(); }

#pragma unroll
        for (int ks = 0; ks < 2; ks++) {
            int kk = ks * 8;
            unsigned a[4][4], b[8][2];
#pragma unroll
            for (int im = 0; im < 4; im++) {
                int rb = wm + im * 16;
                a[im][0] = As[stg][(rb + lr) * SA + kk + lc];
                a[im][1] = As[stg][(rb + lr + 8) * SA + kk + lc];
                a[im][2] = As[stg][(rb + lr) * SA + kk + lc + 4];
                a[im][3] = As[stg][(rb + lr + 8) * SA + kk + lc + 4];
            }
#pragma unroll
            for (int in_ = 0; in_ < 8; in_++) {
                int nb = wn + in_ * 8 + lr;
                b[in_][0] = Bs[stg][(kk + lc) * SB + nb];
                b[in_][1] = Bs[stg][(kk + lc + 4) * SB + nb];
            }
#pragma unroll
            for (int im = 0; im < 4; im++)
#pragma unroll
                for (int in_ = 0; in_ < 8; in_++)
                    mma_tf32(acc[im][in_], a[im], b[in_]);
        }
    }

    // ---- epilogue ----
#pragma unroll
    for (int im = 0; im < 4; im++) {
#pragma unroll
        for (int in_ = 0; in_ < 8; in_++) {
            int col = n0 + wn + in_ * 8 + lc * 2;
            float bias0 = bias[(size_t)e * NTOT + col];
            float bias1 = bias[(size_t)e * NTOT + col + 1];
#pragma unroll
            for (int half = 0; half < 2; half++) {
                int r = wm + im * 16 + lr + half * 8;
                int grow = m0 + r;
                if (grow < cnt) {
                    float v0 = acc[im][in_][half * 2 + 0] + bias0;
                    float v1 = acc[im][in_][half * 2 + 1] + bias1;
                    if (IS_G1) {
                        size_t hrow = (size_t)(off + grow);
                        g_H[hrow * DF + col]     = f2tf32(gelu_exact(v0));
                        g_H[hrow * DF + col + 1] = f2tf32(gelu_exact(v1));
                    } else {
                        int tok = g_tok[e * T_TOKENS + grow];
                        float w = g_w[e * T_TOKENS + grow];
                        atomicAdd(&out[(size_t)tok * DM + col], w * v0);
                        atomicAdd(&out[(size_t)tok * DM + col + 1], w * v1);
                    }
                }
            }
        }
    }
}

// ---------------- launch -----------------------------------------------------
extern "C" void kernel_launch(void* const* d_in, const int* in_sizes, int n_in,
                              void* d_out, int out_size) {
    const float* x  = (const float*)d_in[0];
    const float* Wg = (const float*)d_in[1];
    const float* bg = (const float*)d_in[2];
    const float* W1 = (const float*)d_in[3];
    const float* b1 = (const float*)d_in[4];
    const float* W2 = (const float*)d_in[5];
    const float* b2 = (const float*)d_in[6];
    float* out = (float*)d_out;

    int n4 = out_size / 4;
    zero_kernel<<<(n4 + 255) / 256, 256>>>(out, n4);

    // pre-convert operands to tf32 bit images
    {
        unsigned* w1t; cudaGetSymbolAddress((void**)&w1t, g_W1t);
        unsigned* w2t; cudaGetSymbolAddress((void**)&w2t, g_W2t);
        unsigned* xt;  cudaGetSymbolAddress((void**)&xt,  g_xt);
        int nw4 = (N_EXP * DM * DF) / 4;     // 8,388,608
        conv_kernel<<<nw4 / 256, 256>>>((const float4*)W1, (uint4*)w1t, nw4);
        conv_kernel<<<nw4 / 256, 256>>>((const float4*)W2, (uint4*)w2t, nw4);
        int nx4 = (T_TOKENS * DM) / 4;       // 2,097,152
        conv_kernel<<<nx4 / 256, 256>>>((const float4*)x, (uint4*)xt, nx4);
    }

    const int OUT_ELEMS = T_TOKENS * DM;
    int write_logits = (out_size >= OUT_ELEMS + T_TOKENS * N_EXP);
    float* logits = out + OUT_ELEMS;
    gating_kernel<<<T_TOKENS / 8, 256>>>(x, Wg, bg, logits, write_logits);

    scan_kernel<<<1, 1>>>();

    unsigned* w1t; cudaGetSymbolAddress((void**)&w1t, g_W1t);
    unsigned* w2t; cudaGetSymbolAddress((void**)&w2t, g_W2t);
    unsigned* xt;  cudaGetSymbolAddress((void**)&xt,  g_xt);

    dim3 g1(DF / BN, T_TOKENS / BM, N_EXP);
    moe_gemm_fb<1><<<g1, NTHR>>>(xt, w1t, b1, nullptr);

    dim3 g2(DM / BN, T_TOKENS / BM, N_EXP);
    moe_gemm_fb<0><<<g2, NTHR>>>(nullptr, w2t, b2, out);
}

// round 13
// speedup vs baseline: 1.5879x; 1.5879x over previous
#include <cuda_runtime.h>
#include <math.h>
#include <stdint.h>

#define T_TOKENS 8192
#define DM 1024
#define DF 4096
#define N_EXP 8

// ---------------- scratch (__device__ globals) ------------------------------
__device__ int      g_counts[N_EXP];
__device__ int      g_offsets[N_EXP];
__device__ int      g_tok[N_EXP * T_TOKENS];
__device__ float    g_w[N_EXP * T_TOKENS];
__device__ unsigned g_H[(size_t)16384 * DF];          // tf32 bit image
__device__ unsigned g_W1t[(size_t)N_EXP * DM * DF];   // tf32 bit image of W1
__device__ unsigned g_W2t[(size_t)N_EXP * DF * DM];   // tf32 bit image of W2
__device__ unsigned g_xt[(size_t)T_TOKENS * DM];      // tf32 bit image of x

// ---------------- helpers ----------------------------------------------------
__device__ __forceinline__ unsigned f2tf32(float f) {
    unsigned u;
    asm("cvt.rna.tf32.f32 %0, %1;" : "=r"(u) : "f"(f));
    return u;
}

__device__ __forceinline__ void mma_tf32(float c[4], const unsigned a[4], const unsigned b[2]) {
    asm volatile(
        "mma.sync.aligned.m16n8k8.row.col.f32.tf32.tf32.f32 "
        "{%0,%1,%2,%3}, {%4,%5,%6,%7}, {%8,%9}, {%0,%1,%2,%3};\n"
        : "+f"(c[0]), "+f"(c[1]), "+f"(c[2]), "+f"(c[3])
        : "r"(a[0]), "r"(a[1]), "r"(a[2]), "r"(a[3]), "r"(b[0]), "r"(b[1]));
}

__device__ __forceinline__ float gelu_exact(float v) {
    return 0.5f * v * (1.0f + erff(v * 0.70710678118654752f));
}

__device__ __forceinline__ unsigned smem_u32(const void* p) {
    unsigned a;
    asm("{ .reg .u64 t; cvta.to.shared.u64 t, %1; cvt.u32.u64 %0, t; }"
        : "=r"(a) : "l"(p));
    return a;
}

#define CP_ASYNC16(dst, src, sz) \
    asm volatile("cp.async.cg.shared.global [%0], [%1], 16, %2;" \
                 :: "r"(dst), "l"(src), "r"(sz) : "memory")
#define CP_COMMIT() asm volatile("cp.async.commit_group;" ::: "memory")
#define CP_WAIT(n)  asm volatile("cp.async.wait_group %0;" :: "n"(n) : "memory")

// ---------------- conversion: f32 -> tf32 bit image ---------------------------
__global__ void conv_kernel(const float4* __restrict__ s, uint4* __restrict__ d, int n4) {
    int i = blockIdx.x * blockDim.x + threadIdx.x;
    if (i < n4) {
        float4 v = s[i];
        uint4 u;
        u.x = f2tf32(v.x); u.y = f2tf32(v.y);
        u.z = f2tf32(v.z); u.w = f2tf32(v.w);
        d[i] = u;
    }
}

// ---------------- zero out + counters ----------------------------------------
__global__ void zero_kernel(float* __restrict__ out, int n4) {
    int i = blockIdx.x * blockDim.x + threadIdx.x;
    if (i < n4) reinterpret_cast<float4*>(out)[i] = make_float4(0.f, 0.f, 0.f, 0.f);
    if (i < N_EXP) g_counts[i] = 0;
}

// ---------------- gating: one warp per token ---------------------------------
__global__ void gating_kernel(const float* __restrict__ x,
                              const float* __restrict__ Wg,
                              const float* __restrict__ bg,
                              float* __restrict__ logits_out,
                              int write_logits) {
    int warp = threadIdx.x >> 5;
    int lane = threadIdx.x & 31;
    int t = blockIdx.x * (blockDim.x >> 5) + warp;
    if (t >= T_TOKENS) return;

    float acc[8];
#pragma unroll
    for (int e = 0; e < 8; e++) acc[e] = 0.f;

    const float4* x4 = reinterpret_cast<const float4*>(x + (size_t)t * DM);
#pragma unroll
    for (int j = 0; j < 8; j++) {
        int idx4 = j * 32 + lane;
        float4 v = x4[idx4];
        float vv[4] = {v.x, v.y, v.z, v.w};
        int i = idx4 * 4;
#pragma unroll
        for (int c = 0; c < 4; c++) {
            const float4* w4 = reinterpret_cast<const float4*>(Wg + (size_t)(i + c) * 8);
            float4 wa = w4[0], wb = w4[1];
            acc[0] += vv[c] * wa.x; acc[1] += vv[c] * wa.y;
            acc[2] += vv[c] * wa.z; acc[3] += vv[c] * wa.w;
            acc[4] += vv[c] * wb.x; acc[5] += vv[c] * wb.y;
            acc[6] += vv[c] * wb.z; acc[7] += vv[c] * wb.w;
        }
    }
#pragma unroll
    for (int e = 0; e < 8; e++)
#pragma unroll
        for (int o = 16; o > 0; o >>= 1)
            acc[e] += __shfl_xor_sync(0xffffffffu, acc[e], o);

    if (lane == 0) {
        float lg[8];
#pragma unroll
        for (int e = 0; e < 8; e++) lg[e] = acc[e] + bg[e];
        if (write_logits) {
#pragma unroll
            for (int e = 0; e < 8; e++) logits_out[(size_t)t * 8 + e] = lg[e];
        }
        float mx = lg[0];
#pragma unroll
        for (int e = 1; e < 8; e++) mx = fmaxf(mx, lg[e]);
        float p[8], s = 0.f;
#pragma unroll
        for (int e = 0; e < 8; e++) { p[e] = expf(lg[e] - mx); s += p[e]; }
        int i1 = 0;
#pragma unroll
        for (int e = 1; e < 8; e++) if (p[e] > p[i1]) i1 = e;
        int i2 = -1;
#pragma unroll
        for (int e = 0; e < 8; e++) {
            if (e == i1) continue;
            if (i2 < 0 || p[e] > p[i2]) i2 = e;
        }
        float w1 = p[i1] / s, w2 = p[i2] / s;
        int pos1 = atomicAdd(&g_counts[i1], 1);
        g_tok[i1 * T_TOKENS + pos1] = t;
        g_w[i1 * T_TOKENS + pos1] = w1;
        int pos2 = atomicAdd(&g_counts[i2], 1);
        g_tok[i2 * T_TOKENS + pos2] = t;
        g_w[i2 * T_TOKENS + pos2] = w2;
    }
}

__global__ void scan_kernel() {
    if (threadIdx.x == 0 && blockIdx.x == 0) {
        int s = 0;
        for (int e = 0; e < N_EXP; e++) { g_offsets[e] = s; s += g_counts[e]; }
    }
}

// ---------------- tiled tf32 GEMM: 128x128 CTA, 4 warps of 64x64 --------------
// cp.async 3-stage pipeline; operands pre-converted tf32 (no cvt in hot loop).
// A group is committed EVERY iteration (empty past the end) so wait_group 1
// always forces completion of the tile about to be consumed — including the
// final tile (the round-11 race).
#define BM 128
#define BN 128
#define BK 16
#define SA 20    // A smem row stride (words)
#define SB 136   // B smem row stride (words)
#define NTHR 128
#define NSTG 3

// IS_G1=1: A = g_xt gathered by token, out = g_H (gelu+b1, tf32 bits)
// IS_G1=0: A = g_H rows,               out = atomic combine into out (b2, weights)
template<int IS_G1>
__global__ __launch_bounds__(NTHR, 2) void moe_gemm_fb(
    const unsigned* __restrict__ Asrc0,
    const unsigned* __restrict__ Wt,
    const float* __restrict__ bias,
    float* __restrict__ out)
{
    constexpr int KTOT = IS_G1 ? DM : DF;
    constexpr int NTOT = IS_G1 ? DF : DM;

    int e = blockIdx.z;
    int cnt = g_counts[e];
    int m0 = blockIdx.y * BM;
    if (m0 >= cnt) return;
    int n0 = blockIdx.x * BN;
    int off = g_offsets[e];
    const unsigned* W = Wt + (size_t)e * KTOT * NTOT;
    const unsigned* A = IS_G1 ? Asrc0 : g_H;

    __shared__ unsigned As[NSTG][BM * SA];
    __shared__ unsigned Bs[NSTG][BK * SB];

    int tid = threadIdx.x;
    int warp = tid >> 5, lane = tid & 31;
    int wm = (warp >> 1) * 64, wn = (warp & 1) * 64;
    int lr = lane >> 2, lc = lane & 3;

    unsigned aBase = smem_u32(&As[0][0]);
    unsigned bBase = smem_u32(&Bs[0][0]);

    // A-load rows: r = tid>>2 + h*32 for h = 0..3
    int rowv[4];
#pragma unroll
    for (int h = 0; h < 4; h++) {
        int r = (tid >> 2) + h * 32;
        int grow = m0 + r;
        if (grow >= cnt) rowv[h] = -1;
        else rowv[h] = IS_G1 ? g_tok[e * T_TOKENS + grow] : (off + grow);
    }

    float acc[4][8][4];
#pragma unroll
    for (int im = 0; im < 4; im++)
#pragma unroll
        for (int in_ = 0; in_ < 8; in_++)
#pragma unroll
            for (int q = 0; q < 4; q++) acc[im][in_][q] = 0.f;

    auto issue = [&](int kt, int stg) {
        int k0 = kt * BK;
        unsigned abuf = aBase + stg * (BM * SA * 4);
        unsigned bbuf = bBase + stg * (BK * SB * 4);
#pragma unroll
        for (int h = 0; h < 4; h++) {
            int r = (tid >> 2) + h * 32;
            unsigned dst = abuf + r * (SA * 4) + (tid & 3) * 16;
            int rv = rowv[h];
            const unsigned* src = A + (size_t)(rv < 0 ? 0 : rv) * KTOT + k0 + (tid & 3) * 4;
            int sz = (rv < 0) ? 0 : 16;
            CP_ASYNC16(dst, src, sz);
        }
#pragma unroll
        for (int h = 0; h < 4; h++) {
            int idx = tid + h * NTHR;
            int k = idx >> 5, c = (idx & 31) * 4;
            unsigned dst = bbuf + k * (SB * 4) + c * 4;
            const unsigned* src = W + (size_t)(k0 + k) * NTOT + n0 + c;
            CP_ASYNC16(dst, src, 16);
        }
    };

    const int nk = KTOT / BK;
    issue(0, 0); CP_COMMIT();
    issue(1, 1); CP_COMMIT();

    for (int kt = 0; kt < nk; kt++) {
        int stg = kt % NSTG;
        CP_WAIT(1);
        __syncthreads();
        int nxt = kt + 2;
        if (nxt < nk) issue(nxt, nxt % NSTG);
        CP_COMMIT();   // commit EVERY iteration (empty near the tail) so the
                       // pending-group count stays at 2 and wait_group 1
                       // always completes tile kt before it is read.

#pragma unroll
        for (int ks = 0; ks < 2; ks++) {
            int kk = ks * 8;
            unsigned a[4][4], b[8][2];
#pragma unroll
            for (int im = 0; im < 4; im++) {
                int rb = wm + im * 16;
                a[im][0] = As[stg][(rb + lr) * SA + kk + lc];
                a[im][1] = As[stg][(rb + lr + 8) * SA + kk + lc];
                a[im][2] = As[stg][(rb + lr) * SA + kk + lc + 4];
                a[im][3] = As[stg][(rb + lr + 8) * SA + kk + lc + 4];
            }
#pragma unroll
            for (int in_ = 0; in_ < 8; in_++) {
                int nb = wn + in_ * 8 + lr;
                b[in_][0] = Bs[stg][(kk + lc) * SB + nb];
                b[in_][1] = Bs[stg][(kk + lc + 4) * SB + nb];
            }
#pragma unroll
            for (int im = 0; im < 4; im++)
#pragma unroll
                for (int in_ = 0; in_ < 8; in_++)
                    mma_tf32(acc[im][in_], a[im], b[in_]);
        }
    }

    // ---- epilogue ----
#pragma unroll
    for (int im = 0; im < 4; im++) {
#pragma unroll
        for (int in_ = 0; in_ < 8; in_++) {
            int col = n0 + wn + in_ * 8 + lc * 2;
            float bias0 = bias[(size_t)e * NTOT + col];
            float bias1 = bias[(size_t)e * NTOT + col + 1];
#pragma unroll
            for (int half = 0; half < 2; half++) {
                int r = wm + im * 16 + lr + half * 8;
                int grow = m0 + r;
                if (grow < cnt) {
                    float v0 = acc[im][in_][half * 2 + 0] + bias0;
                    float v1 = acc[im][in_][half * 2 + 1] + bias1;
                    if (IS_G1) {
                        size_t hrow = (size_t)(off + grow);
                        g_H[hrow * DF + col]     = f2tf32(gelu_exact(v0));
                        g_H[hrow * DF + col + 1] = f2tf32(gelu_exact(v1));
                    } else {
                        int tok = g_tok[e * T_TOKENS + grow];
                        float w = g_w[e * T_TOKENS + grow];
                        atomicAdd(&out[(size_t)tok * DM + col], w * v0);
                        atomicAdd(&out[(size_t)tok * DM + col + 1], w * v1);
                    }
                }
            }
        }
    }
}

// ---------------- launch -----------------------------------------------------
extern "C" void kernel_launch(void* const* d_in, const int* in_sizes, int n_in,
                              void* d_out, int out_size) {
    const float* x  = (const float*)d_in[0];
    const float* Wg = (const float*)d_in[1];
    const float* bg = (const float*)d_in[2];
    const float* W1 = (const float*)d_in[3];
    const float* b1 = (const float*)d_in[4];
    const float* W2 = (const float*)d_in[5];
    const float* b2 = (const float*)d_in[6];
    float* out = (float*)d_out;

    int n4 = out_size / 4;
    zero_kernel<<<(n4 + 255) / 256, 256>>>(out, n4);

    // pre-convert operands to tf32 bit images
    {
        unsigned* w1t; cudaGetSymbolAddress((void**)&w1t, g_W1t);
        unsigned* w2t; cudaGetSymbolAddress((void**)&w2t, g_W2t);
        unsigned* xt;  cudaGetSymbolAddress((void**)&xt,  g_xt);
        int nw4 = (N_EXP * DM * DF) / 4;     // 8,388,608
        conv_kernel<<<nw4 / 256, 256>>>((const float4*)W1, (uint4*)w1t, nw4);
        conv_kernel<<<nw4 / 256, 256>>>((const float4*)W2, (uint4*)w2t, nw4);
        int nx4 = (T_TOKENS * DM) / 4;       // 2,097,152
        conv_kernel<<<nx4 / 256, 256>>>((const float4*)x, (uint4*)xt, nx4);
    }

    const int OUT_ELEMS = T_TOKENS * DM;
    int write_logits = (out_size >= OUT_ELEMS + T_TOKENS * N_EXP);
    float* logits = out + OUT_ELEMS;
    gating_kernel<<<T_TOKENS / 8, 256>>>(x, Wg, bg, logits, write_logits);

    scan_kernel<<<1, 1>>>();

    unsigned* w1t; cudaGetSymbolAddress((void**)&w1t, g_W1t);
    unsigned* w2t; cudaGetSymbolAddress((void**)&w2t, g_W2t);
    unsigned* xt;  cudaGetSymbolAddress((void**)&xt,  g_xt);

    dim3 g1(DF / BN, T_TOKENS / BM, N_EXP);
    moe_gemm_fb<1><<<g1, NTHR>>>(xt, w1t, b1, nullptr);

    dim3 g2(DM / BN, T_TOKENS / BM, N_EXP);
    moe_gemm_fb<0><<<g2, NTHR>>>(nullptr, w2t, b2, out);
}

// round 14
// speedup vs baseline: 1.6886x; 1.0634x over previous
#include <cuda_runtime.h>
#include <math.h>
#include <stdint.h>

#define T_TOKENS 8192
#define DM 1024
#define DF 4096
#define N_EXP 8

// ---------------- scratch (__device__ globals) ------------------------------
__device__ int      g_counts[N_EXP];
__device__ int      g_offsets[N_EXP];
__device__ int      g_tok[N_EXP * T_TOKENS];
__device__ float    g_w[N_EXP * T_TOKENS];
__device__ unsigned g_H[(size_t)16384 * DF];          // tf32 bits, pair-permuted rows
__device__ unsigned g_W1t[(size_t)N_EXP * DM * DF];   // tf32 bits, pair-permuted
__device__ unsigned g_W2t[(size_t)N_EXP * DF * DM];   // tf32 bits, pair-permuted
__device__ unsigned g_xt[(size_t)T_TOKENS * DM];      // tf32 bits, pair-permuted rows

// ---------------- helpers ----------------------------------------------------
__device__ __forceinline__ unsigned f2tf32(float f) {
    unsigned u;
    asm("cvt.rna.tf32.f32 %0, %1;" : "=r"(u) : "f"(f));
    return u;
}

__device__ __forceinline__ void mma_tf32(float c[4], const unsigned a[4], const unsigned b[2]) {
    asm volatile(
        "mma.sync.aligned.m16n8k8.row.col.f32.tf32.tf32.f32 "
        "{%0,%1,%2,%3}, {%4,%5,%6,%7}, {%8,%9}, {%0,%1,%2,%3};\n"
        : "+f"(c[0]), "+f"(c[1]), "+f"(c[2]), "+f"(c[3])
        : "r"(a[0]), "r"(a[1]), "r"(a[2]), "r"(a[3]), "r"(b[0]), "r"(b[1]));
}

__device__ __forceinline__ float gelu_exact(float v) {
    return 0.5f * v * (1.0f + erff(v * 0.70710678118654752f));
}

__device__ __forceinline__ unsigned smem_u32(const void* p) {
    unsigned a;
    asm("{ .reg .u64 t; cvta.to.shared.u64 t, %1; cvt.u32.u64 %0, t; }"
        : "=r"(a) : "l"(p));
    return a;
}

#define CP_ASYNC16(dst, src, sz) \
    asm volatile("cp.async.cg.shared.global [%0], [%1], 16, %2;" \
                 :: "r"(dst), "l"(src), "r"(sz) : "memory")
#define CP_COMMIT() asm volatile("cp.async.commit_group;" ::: "memory")
#define CP_WAIT(n)  asm volatile("cp.async.wait_group %0;" :: "n"(n) : "memory")

// within-row k permutation: k -> (k>>4)*16 + pair*2 + sel
// pair = ((k>>3)&1)*4 + (k&3), sel = (k>>2)&1. Pairs are (k, k+4) adjacent.
__device__ __forceinline__ int kperm(int k) {
    return (k >> 4) * 16 + ((((k >> 3) & 1) * 4 + (k & 3)) * 2) + ((k >> 2) & 1);
}

// ---------------- conversions -------------------------------------------------
// x -> tf32 bits, per-row pair permutation
__global__ void convx_kernel(const float4* __restrict__ s, unsigned* __restrict__ d, int n4) {
    int i = blockIdx.x * blockDim.x + threadIdx.x;
    if (i >= n4) return;
    float4 v = s[i];
    int t = i >> 8;               // DM/4 = 256 float4 per row
    int k = (i & 255) * 4;
    unsigned* row = d + (size_t)t * DM;
    row[kperm(k + 0)] = f2tf32(v.x);
    row[kperm(k + 1)] = f2tf32(v.y);
    row[kperm(k + 2)] = f2tf32(v.z);
    row[kperm(k + 3)] = f2tf32(v.w);
}

// W[e][k][n] -> pair-permuted tf32: word((e*(K/16)+kb)*8+pr, n*2+sel)
// value = W[kb*16 + (pr>>2)*8 + (pr&3) + sel*4][n]
__global__ void convW_kernel(const float* __restrict__ W, unsigned* __restrict__ Wp,
                             int KTOT, int NTOT) {
    int i = blockIdx.x * blockDim.x + threadIdx.x;   // one thread = 4 n values
    int nquads = NTOT >> 2;
    int total = N_EXP * (KTOT >> 4) * 8 * nquads;
    if (i >= total) return;
    int n4 = i % nquads;
    int r  = i / nquads;
    int pr = r & 7;
    int r2 = r >> 3;
    int kb = r2 % (KTOT >> 4);
    int e  = r2 / (KTOT >> 4);
    int k1 = kb * 16 + ((pr >> 2) * 8) + (pr & 3);
    int k2 = k1 + 4;
    const float4 v1 = *reinterpret_cast<const float4*>(
        W + ((size_t)e * KTOT + k1) * NTOT + n4 * 4);
    const float4 v2 = *reinterpret_cast<const float4*>(
        W + ((size_t)e * KTOT + k2) * NTOT + n4 * 4);
    uint4 o0, o1;
    o0.x = f2tf32(v1.x); o0.y = f2tf32(v2.x); o0.z = f2tf32(v1.y); o0.w = f2tf32(v2.y);
    o1.x = f2tf32(v1.z); o1.y = f2tf32(v2.z); o1.z = f2tf32(v1.w); o1.w = f2tf32(v2.w);
    unsigned* dst = Wp + ((size_t)(e * (KTOT >> 4) + kb) * 8 + pr) * (size_t)(NTOT * 2)
                       + (size_t)n4 * 8;
    *reinterpret_cast<uint4*>(dst)     = o0;
    *reinterpret_cast<uint4*>(dst + 4) = o1;
}

// ---------------- zero out + counters ----------------------------------------
__global__ void zero_kernel(float* __restrict__ out, int n4) {
    int i = blockIdx.x * blockDim.x + threadIdx.x;
    if (i < n4) reinterpret_cast<float4*>(out)[i] = make_float4(0.f, 0.f, 0.f, 0.f);
    if (i < N_EXP) g_counts[i] = 0;
}

// ---------------- gating: one warp per token ---------------------------------
__global__ void gating_kernel(const float* __restrict__ x,
                              const float* __restrict__ Wg,
                              const float* __restrict__ bg,
                              float* __restrict__ logits_out,
                              int write_logits) {
    int warp = threadIdx.x >> 5;
    int lane = threadIdx.x & 31;
    int t = blockIdx.x * (blockDim.x >> 5) + warp;
    if (t >= T_TOKENS) return;

    float acc[8];
#pragma unroll
    for (int e = 0; e < 8; e++) acc[e] = 0.f;

    const float4* x4 = reinterpret_cast<const float4*>(x + (size_t)t * DM);
#pragma unroll
    for (int j = 0; j < 8; j++) {
        int idx4 = j * 32 + lane;
        float4 v = x4[idx4];
        float vv[4] = {v.x, v.y, v.z, v.w};
        int i = idx4 * 4;
#pragma unroll
        for (int c = 0; c < 4; c++) {
            const float4* w4 = reinterpret_cast<const float4*>(Wg + (size_t)(i + c) * 8);
            float4 wa = w4[0], wb = w4[1];
            acc[0] += vv[c] * wa.x; acc[1] += vv[c] * wa.y;
            acc[2] += vv[c] * wa.z; acc[3] += vv[c] * wa.w;
            acc[4] += vv[c] * wb.x; acc[5] += vv[c] * wb.y;
            acc[6] += vv[c] * wb.z; acc[7] += vv[c] * wb.w;
        }
    }
#pragma unroll
    for (int e = 0; e < 8; e++)
#pragma unroll
        for (int o = 16; o > 0; o >>= 1)
            acc[e] += __shfl_xor_sync(0xffffffffu, acc[e], o);

    if (lane == 0) {
        float lg[8];
#pragma unroll
        for (int e = 0; e < 8; e++) lg[e] = acc[e] + bg[e];
        if (write_logits) {
#pragma unroll
            for (int e = 0; e < 8; e++) logits_out[(size_t)t * 8 + e] = lg[e];
        }
        float mx = lg[0];
#pragma unroll
        for (int e = 1; e < 8; e++) mx = fmaxf(mx, lg[e]);
        float p[8], s = 0.f;
#pragma unroll
        for (int e = 0; e < 8; e++) { p[e] = expf(lg[e] - mx); s += p[e]; }
        int i1 = 0;
#pragma unroll
        for (int e = 1; e < 8; e++) if (p[e] > p[i1]) i1 = e;
        int i2 = -1;
#pragma unroll
        for (int e = 0; e < 8; e++) {
            if (e == i1) continue;
            if (i2 < 0 || p[e] > p[i2]) i2 = e;
        }
        float w1 = p[i1] / s, w2 = p[i2] / s;
        int pos1 = atomicAdd(&g_counts[i1], 1);
        g_tok[i1 * T_TOKENS + pos1] = t;
        g_w[i1 * T_TOKENS + pos1] = w1;
        int pos2 = atomicAdd(&g_counts[i2], 1);
        g_tok[i2 * T_TOKENS + pos2] = t;
        g_w[i2 * T_TOKENS + pos2] = w2;
    }
}

__global__ void scan_kernel() {
    if (threadIdx.x == 0 && blockIdx.x == 0) {
        int s = 0;
        for (int e = 0; e < N_EXP; e++) { g_offsets[e] = s; s += g_counts[e]; }
    }
}

// ---------------- tiled tf32 GEMM: 128x128 CTA, 4 warps of 64x64, BK=32 -------
// Pair-packed smem layouts -> all fragment loads are conflict-free LDS.64.
// cp.async 3-stage pipeline, one barrier per BK32 tile; commit every iter.
#define BM 128
#define BN 128
#define BK 32
#define SAW 40                 // A row stride (words): banks lr*8+lc*2 conflict-free
#define SBW 264                // B pair-row stride (words): banks lc*8+lr*2 conflict-free
#define A_WORDS (BM * SAW)     // 5120
#define B_WORDS (16 * SBW)     // 4224
#define STG_WORDS (A_WORDS + B_WORDS)
#define NTHR 128
#define NSTG 3
#define GEMM_SMEM (NSTG * STG_WORDS * 4)   // 112128 B

// IS_G1=1: A = g_xt gathered by token, out = g_H (gelu+b1, pair-permuted tf32)
// IS_G1=0: A = g_H rows,               out = atomic combine into out (b2, weights)
template<int IS_G1>
__global__ __launch_bounds__(NTHR, 2) void moe_gemm_fb(
    const unsigned* __restrict__ Asrc0,
    const unsigned* __restrict__ Wt,
    const float* __restrict__ bias,
    float* __restrict__ out)
{
    constexpr int KTOT = IS_G1 ? DM : DF;
    constexpr int NTOT = IS_G1 ? DF : DM;

    int e = blockIdx.z;
    int cnt = g_counts[e];
    int m0 = blockIdx.y * BM;
    if (m0 >= cnt) return;
    int n0 = blockIdx.x * BN;
    int off = g_offsets[e];
    const unsigned* Wexp = Wt + (size_t)e * KTOT * NTOT;   // pair-permuted words
    const unsigned* A = IS_G1 ? Asrc0 : g_H;

    extern __shared__ unsigned dsm[];
    unsigned sBase = smem_u32(dsm);

    int tid = threadIdx.x;
    int warp = tid >> 5, lane = tid & 31;
    int wm = (warp >> 1) * 64, wn = (warp & 1) * 64;
    int lr = lane >> 2, lc = lane & 3;

    // A-load rows: r = (tid>>3) + h*16, h = 0..7
    int rowv[8];
#pragma unroll
    for (int h = 0; h < 8; h++) {
        int r = (tid >> 3) + h * 16;
        int grow = m0 + r;
        if (grow >= cnt) rowv[h] = -1;
        else rowv[h] = IS_G1 ? g_tok[e * T_TOKENS + grow] : (off + grow);
    }

    float acc[4][8][4];
#pragma unroll
    for (int im = 0; im < 4; im++)
#pragma unroll
        for (int in_ = 0; in_ < 8; in_++)
#pragma unroll
            for (int q = 0; q < 4; q++) acc[im][in_][q] = 0.f;

    auto issue = [&](int kt, int stg) {
        int k0 = kt * BK;
        unsigned abuf = sBase + stg * (STG_WORDS * 4);
        unsigned bbuf = abuf + A_WORDS * 4;
        // A: 128 rows x 128B (pair-permuted rows are contiguous per 16-block)
#pragma unroll
        for (int h = 0; h < 8; h++) {
            int r = (tid >> 3) + h * 16;
            int c = tid & 7;
            unsigned dst = abuf + r * (SAW * 4) + c * 16;
            int rv = rowv[h];
            const unsigned* src = A + (size_t)(rv < 0 ? 0 : rv) * KTOT + k0 + c * 4;
            int sz = (rv < 0) ? 0 : 16;
            CP_ASYNC16(dst, src, sz);
        }
        // B: 16 pair-rows x 1024B
        int kb0 = k0 >> 4;
#pragma unroll
        for (int h = 0; h < 8; h++) {
            int idx = tid + h * NTHR;   // 0..1023
            int row = idx >> 6;         // 0..15
            int c = idx & 63;           // 0..63 (16B chunks)
            unsigned dst = bbuf + row * (SBW * 4) + c * 16;
            const unsigned* src = Wexp
                + ((size_t)(kb0 + (row >> 3)) * 8 + (row & 7)) * (size_t)(NTOT * 2)
                + (size_t)n0 * 2 + c * 4;
            CP_ASYNC16(dst, src, 16);
        }
    };

    const int nk = KTOT / BK;
    issue(0, 0); CP_COMMIT();
    issue(1, 1); CP_COMMIT();

    for (int kt = 0; kt < nk; kt++) {
        int stg = kt % NSTG;
        CP_WAIT(1);
        __syncthreads();
        int nxt = kt + 2;
        if (nxt < nk) issue(nxt, nxt % NSTG);
        CP_COMMIT();   // keep pending-group count uniform (round-13 race fix)

        const unsigned* As_ = dsm + stg * STG_WORDS;
        const unsigned* Bs_ = As_ + A_WORDS;

#pragma unroll
        for (int s = 0; s < 4; s++) {
            int abase = (s >> 1) * 16 + ((s & 1) * 4 + lc) * 2;  // word off in A row
            int rowb = (s >> 1) * 8 + (s & 1) * 4 + lc;          // B pair-row
            unsigned a[4][4], b[8][2];
#pragma unroll
            for (int im = 0; im < 4; im++) {
                int row = wm + im * 16 + lr;
                uint2 lo = *reinterpret_cast<const uint2*>(&As_[row * SAW + abase]);
                uint2 hi = *reinterpret_cast<const uint2*>(&As_[(row + 8) * SAW + abase]);
                a[im][0] = lo.x; a[im][1] = hi.x; a[im][2] = lo.y; a[im][3] = hi.y;
            }
#pragma unroll
            for (int in_ = 0; in_ < 8; in_++) {
                uint2 bb = *reinterpret_cast<const uint2*>(
                    &Bs_[rowb * SBW + (wn + in_ * 8 + lr) * 2]);
                b[in_][0] = bb.x; b[in_][1] = bb.y;
            }
#pragma unroll
            for (int im = 0; im < 4; im++)
#pragma unroll
                for (int in_ = 0; in_ < 8; in_++)
                    mma_tf32(acc[im][in_], a[im], b[in_]);
        }
    }

    // ---- epilogue ----
#pragma unroll
    for (int im = 0; im < 4; im++) {
#pragma unroll
        for (int in_ = 0; in_ < 8; in_++) {
            int col = n0 + wn + in_ * 8 + lc * 2;
            float bias0 = bias[(size_t)e * NTOT + col];
            float bias1 = bias[(size_t)e * NTOT + col + 1];
#pragma unroll
            for (int half = 0; half < 2; half++) {
                int r = wm + im * 16 + lr + half * 8;
                int grow = m0 + r;
                if (grow < cnt) {
                    float v0 = acc[im][in_][half * 2 + 0] + bias0;
                    float v1 = acc[im][in_][half * 2 + 1] + bias1;
                    if (IS_G1) {
                        size_t hrow = (size_t)(off + grow);
                        // pair-permuted tf32 store (GEMM2 consumes directly)
                        g_H[hrow * DF + kperm(col)]     = f2tf32(gelu_exact(v0));
                        g_H[hrow * DF + kperm(col + 1)] = f2tf32(gelu_exact(v1));
                    } else {
                        int tok = g_tok[e * T_TOKENS + grow];
                        float w = g_w[e * T_TOKENS + grow];
                        atomicAdd(&out[(size_t)tok * DM + col], w * v0);
                        atomicAdd(&out[(size_t)tok * DM + col + 1], w * v1);
                    }
                }
            }
        }
    }
}

// ---------------- launch -----------------------------------------------------
extern "C" void kernel_launch(void* const* d_in, const int* in_sizes, int n_in,
                              void* d_out, int out_size) {
    const float* x  = (const float*)d_in[0];
    const float* Wg = (const float*)d_in[1];
    const float* bg = (const float*)d_in[2];
    const float* W1 = (const float*)d_in[3];
    const float* b1 = (const float*)d_in[4];
    const float* W2 = (const float*)d_in[5];
    const float* b2 = (const float*)d_in[6];
    float* out = (float*)d_out;

    cudaFuncSetAttribute(moe_gemm_fb<1>,
                         cudaFuncAttributeMaxDynamicSharedMemorySize, GEMM_SMEM);
    cudaFuncSetAttribute(moe_gemm_fb<0>,
                         cudaFuncAttributeMaxDynamicSharedMemorySize, GEMM_SMEM);

    int n4 = out_size / 4;
    zero_kernel<<<(n4 + 255) / 256, 256>>>(out, n4);

    unsigned* w1t; cudaGetSymbolAddress((void**)&w1t, g_W1t);
    unsigned* w2t; cudaGetSymbolAddress((void**)&w2t, g_W2t);
    unsigned* xt;  cudaGetSymbolAddress((void**)&xt,  g_xt);

    // pre-convert operands to pair-permuted tf32 bit images
    {
        int tW1 = N_EXP * (DM >> 4) * 8 * (DF >> 2);   // 4,194,304
        convW_kernel<<<(tW1 + 255) / 256, 256>>>(W1, w1t, DM, DF);
        int tW2 = N_EXP * (DF >> 4) * 8 * (DM >> 2);   // 4,194,304
        convW_kernel<<<(tW2 + 255) / 256, 256>>>(W2, w2t, DF, DM);
        int nx4 = (T_TOKENS * DM) / 4;                 // 2,097,152
        convx_kernel<<<(nx4 + 255) / 256, 256>>>((const float4*)x, xt, nx4);
    }

    const int OUT_ELEMS = T_TOKENS * DM;
    int write_logits = (out_size >= OUT_ELEMS + T_TOKENS * N_EXP);
    float* logits = out + OUT_ELEMS;
    gating_kernel<<<T_TOKENS / 8, 256>>>(x, Wg, bg, logits, write_logits);

    scan_kernel<<<1, 1>>>();

    dim3 g1(DF / BN, T_TOKENS / BM, N_EXP);
    moe_gemm_fb<1><<<g1, NTHR, GEMM_SMEM>>>(xt, w1t, b1, nullptr);

    dim3 g2(DM / BN, T_TOKENS / BM, N_EXP);
    moe_gemm_fb<0><<<g2, NTHR, GEMM_SMEM>>>(nullptr, w2t, b2, out);
}